// round 5
// baseline (speedup 1.0000x reference)
#include <cuda_runtime.h>

// out[to_i[j]] = mat_i[from_i[j]], 3 segments, D=64 fp32 rows (256B).
// 16 threads per row (one float4 each). Each thread handles U=8 rows spaced
// totalRows/U apart (perfect intra-group coalescing preserved), software-
// pipelined: all index loads -> all data loads (MLP=8) -> all stores.
// Phase structure keeps src pointers dead after the load phase to bound
// register pressure.

#define D4 16   // D=64 floats = 16 float4
#define U  8    // rows per thread

__global__ void __launch_bounds__(256)
multi_index_select_kernel(const float4* __restrict__ m0,
                          const float4* __restrict__ m1,
                          const float4* __restrict__ m2,
                          const int*    __restrict__ f0,
                          const int*    __restrict__ f1,
                          const int*    __restrict__ f2,
                          const int*    __restrict__ t0,
                          const int*    __restrict__ t1,
                          const int*    __restrict__ t2,
                          float4*       __restrict__ out,
                          int L, int totalRows, int rowStride)
{
    const int tid  = blockIdx.x * blockDim.x + threadIdx.x;
    const int q    = tid & (D4 - 1);
    const int row0 = tid >> 4;

    float4*       dstp[U];
    float4        v[U];
    bool          act[U];

    // Phase 1: resolve segments, issue index loads, build BOTH address sets.
    // src pointers are consumed immediately by the data loads in phase 2 of
    // the same unrolled iteration group, so they don't stay live across all U.
    const float4* srcp[U];
    #pragma unroll
    for (int k = 0; k < U; k++) {
        const int row = row0 + k * rowStride;
        act[k] = (row < totalRows);
        const float4* m; const int* f; const int* t; int r;
        if (row < L)          { m = m0; f = f0; t = t0; r = row;         }
        else if (row < 2 * L) { m = m1; f = f1; t = t1; r = row - L;     }
        else                  { m = m2; f = f2; t = t2; r = row - 2 * L; }
        const int rr = act[k] ? r : 0;
        const int s  = __ldg(f + rr);
        const int d  = __ldg(t + rr);
        srcp[k] = m   + (size_t)s * D4 + q;
        dstp[k] = out + (size_t)d * D4 + q;
    }

    // Phase 2: U independent 16B loads in flight per thread.
    #pragma unroll
    for (int k = 0; k < U; k++) {
        if (act[k]) v[k] = __ldg(srcp[k]);
    }

    // Phase 3: stores (predicated; no branch).
    #pragma unroll
    for (int k = 0; k < U; k++) {
        if (act[k]) *dstp[k] = v[k];
    }
}

extern "C" void kernel_launch(void* const* d_in, const int* in_sizes, int n_in,
                              void* d_out, int out_size)
{
    const float4* m0 = (const float4*)d_in[0];
    const float4* m1 = (const float4*)d_in[1];
    const float4* m2 = (const float4*)d_in[2];
    const int*    f0 = (const int*)d_in[3];
    const int*    f1 = (const int*)d_in[4];
    const int*    f2 = (const int*)d_in[5];
    const int*    t0 = (const int*)d_in[6];
    const int*    t1 = (const int*)d_in[7];
    const int*    t2 = (const int*)d_in[8];
    float4* out = (float4*)d_out;

    const int L         = in_sizes[3];               // length of from0
    const int totalRows = 3 * L;
    const int rowStride = (totalRows + U - 1) / U;   // rows covered per k-step
    const long long threads = (long long)rowStride * D4;
    const int block = 256;
    const int grid  = (int)((threads + block - 1) / block);

    multi_index_select_kernel<<<grid, block>>>(m0, m1, m2,
                                               f0, f1, f2,
                                               t0, t1, t2,
                                               out, L, totalRows, rowStride);
}

// round 6
// speedup vs baseline: 1.1713x; 1.1713x over previous
#include <cuda_runtime.h>

// out[to_i[j]] = mat_i[from_i[j]], 3 segments of L rows, D=64 fp32 (256B/row).
// 16 threads per row (one float4 each). U=6 rows/thread with COMPILE-TIME
// segment mapping: thread handles rows {r0, r0+L/2} of each segment, so there
// is no runtime segment branch, no predicate array, no pointer-select — just
// 12 coalesced index loads, 6 independent LDG.128 (MLP=6), 6 STG.128.
// Low register pressure keeps occupancy ~75% (the U=8 variant died at 50 regs).

#define D4 16   // D=64 floats = 16 float4

__global__ void __launch_bounds__(256)
mis_u6_kernel(const float4* __restrict__ m0,
              const float4* __restrict__ m1,
              const float4* __restrict__ m2,
              const int*    __restrict__ f0,
              const int*    __restrict__ f1,
              const int*    __restrict__ f2,
              const int*    __restrict__ t0,
              const int*    __restrict__ t1,
              const int*    __restrict__ t2,
              float4*       __restrict__ out,
              int halfL)
{
    const int tid = blockIdx.x * blockDim.x + threadIdx.x;
    const int q   = tid & (D4 - 1);
    const int r0  = tid >> 4;                 // [0, halfL)
    if (r0 >= halfL) return;
    const int r1  = r0 + halfL;

    // Phase 1: all 12 index loads (coalesced / warp-broadcast), front-batched.
    const int s0 = __ldg(f0 + r0), d0 = __ldg(t0 + r0);
    const int s1 = __ldg(f0 + r1), d1 = __ldg(t0 + r1);
    const int s2 = __ldg(f1 + r0), d2 = __ldg(t1 + r0);
    const int s3 = __ldg(f1 + r1), d3 = __ldg(t1 + r1);
    const int s4 = __ldg(f2 + r0), d4 = __ldg(t2 + r0);
    const int s5 = __ldg(f2 + r1), d5 = __ldg(t2 + r1);

    // Phase 2: 6 independent 16B gathers in flight.
    float4 v0 = __ldg(m0 + (size_t)s0 * D4 + q);
    float4 v1 = __ldg(m0 + (size_t)s1 * D4 + q);
    float4 v2 = __ldg(m1 + (size_t)s2 * D4 + q);
    float4 v3 = __ldg(m1 + (size_t)s3 * D4 + q);
    float4 v4 = __ldg(m2 + (size_t)s4 * D4 + q);
    float4 v5 = __ldg(m2 + (size_t)s5 * D4 + q);

    // Phase 3: scatters.
    out[(size_t)d0 * D4 + q] = v0;
    out[(size_t)d1 * D4 + q] = v1;
    out[(size_t)d2 * D4 + q] = v2;
    out[(size_t)d3 * D4 + q] = v3;
    out[(size_t)d4 * D4 + q] = v4;
    out[(size_t)d5 * D4 + q] = v5;
}

// Generic fallback (used only if L is odd): one thread per row-float4.
__global__ void __launch_bounds__(256)
mis_generic_kernel(const float4* __restrict__ m0,
                   const float4* __restrict__ m1,
                   const float4* __restrict__ m2,
                   const int*    __restrict__ f0,
                   const int*    __restrict__ f1,
                   const int*    __restrict__ f2,
                   const int*    __restrict__ t0,
                   const int*    __restrict__ t1,
                   const int*    __restrict__ t2,
                   float4*       __restrict__ out,
                   int L)
{
    int tid = blockIdx.x * blockDim.x + threadIdx.x;
    int row = tid >> 4;
    int q   = tid & (D4 - 1);
    if (row >= 3 * L) return;
    const float4* m; const int* f; const int* t; int r;
    if (row < L)          { m = m0; f = f0; t = t0; r = row;         }
    else if (row < 2 * L) { m = m1; f = f1; t = t1; r = row - L;     }
    else                  { m = m2; f = f2; t = t2; r = row - 2 * L; }
    int src = __ldg(f + r);
    int dst = __ldg(t + r);
    out[(size_t)dst * D4 + q] = __ldg(m + (size_t)src * D4 + q);
}

extern "C" void kernel_launch(void* const* d_in, const int* in_sizes, int n_in,
                              void* d_out, int out_size)
{
    const float4* m0 = (const float4*)d_in[0];
    const float4* m1 = (const float4*)d_in[1];
    const float4* m2 = (const float4*)d_in[2];
    const int*    f0 = (const int*)d_in[3];
    const int*    f1 = (const int*)d_in[4];
    const int*    f2 = (const int*)d_in[5];
    const int*    t0 = (const int*)d_in[6];
    const int*    t1 = (const int*)d_in[7];
    const int*    t2 = (const int*)d_in[8];
    float4* out = (float4*)d_out;

    const int L     = in_sizes[3];     // length of from0
    const int block = 256;

    if ((L & 1) == 0) {
        const int halfL = L >> 1;
        const long long threads = (long long)halfL * D4;
        const int grid = (int)((threads + block - 1) / block);
        mis_u6_kernel<<<grid, block>>>(m0, m1, m2, f0, f1, f2,
                                       t0, t1, t2, out, halfL);
    } else {
        const long long threads = (long long)3 * L * D4;
        const int grid = (int)((threads + block - 1) / block);
        mis_generic_kernel<<<grid, block>>>(m0, m1, m2, f0, f1, f2,
                                            t0, t1, t2, out, L);
    }
}